// round 6
// baseline (speedup 1.0000x reference)
#include <cuda_runtime.h>

// Problem constants (fixed shapes)
constexpr int B  = 16;
constexpr int N  = 4096;
constexpr int K  = 32;
constexpr int BN = B * N;   // 65536

constexpr int THREADS      = 512;          // 16 warps
constexpr int WARPS        = 16;
constexpr int TABLE_FLOATS = N * 12;       // 49152 floats = 192 KB
constexpr int STAGE_FLOATS = 384;          // per-warp: 288 rot + 96 trans (one K-quarter x 4 bn)
constexpr int SMEM_BYTES   = (TABLE_FLOATS + WARPS * STAGE_FLOATS) * 4;  // 221184

// ---------------------------------------------------------------------------
// SO(3) projection (Jacobi eigendecomposition of A^T A), per-thread.
// ---------------------------------------------------------------------------
template <int p, int q, int r>
__device__ __forceinline__ void jrot(float S[3][3], float V[3][3]) {
    float spq = S[p][q];
    if (fabsf(spq) > 1e-30f) {
        float tau = (S[q][q] - S[p][p]) / (2.0f * spq);
        float t   = copysignf(1.0f, tau) / (fabsf(tau) + sqrtf(1.0f + tau * tau));
        float c   = rsqrtf(1.0f + t * t);
        float sn  = t * c;
        float spp = S[p][p], sqq = S[q][q];
        S[p][p] = spp - t * spq;
        S[q][q] = sqq + t * spq;
        S[p][q] = 0.0f; S[q][p] = 0.0f;
        float srp = S[r][p], srq = S[r][q];
        S[r][p] = c * srp - sn * srq; S[p][r] = S[r][p];
        S[r][q] = sn * srp + c * srq; S[q][r] = S[r][q];
#pragma unroll
        for (int i = 0; i < 3; i++) {
            float vip = V[i][p], viq = V[i][q];
            V[i][p] = c * vip - sn * viq;
            V[i][q] = sn * vip + c * viq;
        }
    }
}

__device__ __forceinline__ void svd_project_write(const float* stash, float4* o) {
    // SVD is invariant to positive scaling: use unnormalized rot sums
    float a[3][3] = {{stash[0], stash[1], stash[2]},
                     {stash[3], stash[4], stash[5]},
                     {stash[6], stash[7], stash[8]}};
    float inv = __fdividef(1.0f, stash[12]);
    float t0 = stash[9] * inv, t1 = stash[10] * inv, t2 = stash[11] * inv;

    float S[3][3];
#pragma unroll
    for (int c = 0; c < 3; c++)
#pragma unroll
        for (int d = c; d < 3; d++) {
            float v = a[0][c] * a[0][d] + a[1][c] * a[1][d] + a[2][c] * a[2][d];
            S[c][d] = v; S[d][c] = v;
        }

    float V[3][3] = {{1, 0, 0}, {0, 1, 0}, {0, 0, 1}};
#pragma unroll
    for (int sweep = 0; sweep < 5; sweep++) {
        jrot<0, 1, 2>(S, V);
        jrot<0, 2, 1>(S, V);
        jrot<1, 2, 0>(S, V);
    }

    float l0 = S[0][0], l1 = S[1][1], l2 = S[2][2];
    float v0x = V[0][0], v0y = V[1][0], v0z = V[2][0];
    float v1x = V[0][1], v1y = V[1][1], v1z = V[2][1];
    float v2x = V[0][2], v2y = V[1][2], v2z = V[2][2];

#define CSWAP(la, lb, ax, ay, az, bx, by, bz)                                  \
    if (la < lb) {                                                             \
        float tmp;                                                             \
        tmp = la; la = lb; lb = tmp;                                           \
        tmp = ax; ax = bx; bx = tmp;                                           \
        tmp = ay; ay = by; by = tmp;                                           \
        tmp = az; az = bz; bz = tmp;                                           \
    }
    CSWAP(l0, l1, v0x, v0y, v0z, v1x, v1y, v1z)
    CSWAP(l0, l2, v0x, v0y, v0z, v2x, v2y, v2z)
    CSWAP(l1, l2, v1x, v1y, v1z, v2x, v2y, v2z)
#undef CSWAP

    float cx = v1y * v2z - v1z * v2y;
    float cy = v1z * v2x - v1x * v2z;
    float cz = v1x * v2y - v1y * v2x;
    float det = v0x * cx + v0y * cy + v0z * cz;
    if (det < 0.0f) { v2x = -v2x; v2y = -v2y; v2z = -v2z; }

    float u0x = a[0][0] * v0x + a[0][1] * v0y + a[0][2] * v0z;
    float u0y = a[1][0] * v0x + a[1][1] * v0y + a[1][2] * v0z;
    float u0z = a[2][0] * v0x + a[2][1] * v0y + a[2][2] * v0z;
    float inv0 = rsqrtf(u0x * u0x + u0y * u0y + u0z * u0z + 1e-30f);
    u0x *= inv0; u0y *= inv0; u0z *= inv0;

    float u1x = a[0][0] * v1x + a[0][1] * v1y + a[0][2] * v1z;
    float u1y = a[1][0] * v1x + a[1][1] * v1y + a[1][2] * v1z;
    float u1z = a[2][0] * v1x + a[2][1] * v1y + a[2][2] * v1z;
    float dp = u0x * u1x + u0y * u1y + u0z * u1z;
    u1x -= dp * u0x; u1y -= dp * u0y; u1z -= dp * u0z;
    float inv1 = rsqrtf(u1x * u1x + u1y * u1y + u1z * u1z + 1e-30f);
    u1x *= inv1; u1y *= inv1; u1z *= inv1;

    float u2x = u0y * u1z - u0z * u1y;
    float u2y = u0z * u1x - u0x * u1z;
    float u2z = u0x * u1y - u0y * u1x;

    float R00 = u0x * v0x + u1x * v1x + u2x * v2x;
    float R01 = u0x * v0y + u1x * v1y + u2x * v2y;
    float R02 = u0x * v0z + u1x * v1z + u2x * v2z;
    float R10 = u0y * v0x + u1y * v1x + u2y * v2x;
    float R11 = u0y * v0y + u1y * v1y + u2y * v2y;
    float R12 = u0y * v0z + u1y * v1z + u2y * v2z;
    float R20 = u0z * v0x + u1z * v1x + u2z * v2x;
    float R21 = u0z * v0y + u1z * v1y + u2z * v2y;
    float R22 = u0z * v0z + u1z * v1z + u2z * v2z;

    o[0] = make_float4(R00, R01, R02, R10);
    o[1] = make_float4(R11, R12, R20, R21);
    o[2] = make_float4(R22, t0, t1, t2);
}

// ---------------------------------------------------------------------------
// Single fused kernel. grid = 128 blocks (8 per batch) x 512 threads.
// Each block loads its batch's full frame table (4096 x [rot9|trans3] = 192KB)
// into smem, then each warp owns exactly one 32-bn chunk (2048 warps = 2048
// chunks): 8 iterations x 4 bn, 8 lanes per bn, K staged in quarters of 8
// neighbors through a 1.5KB per-warp smem buffer. Frame gathers are LDS.128
// from the table (no gmem random access at all). After each iteration's
// 8-lane butterfly reduce, results are stashed onto lane it*4+g; the epilogue
// runs 32 fully-parallel Jacobi-SVD projections and writes the output.
// ---------------------------------------------------------------------------
__global__ __launch_bounds__(THREADS) void fused_backbone_kernel(
    const float* __restrict__ frames_rot,
    const float* __restrict__ frames_trans,
    const float* __restrict__ pair_rot,
    const float* __restrict__ pair_trans,
    const float* __restrict__ conf,
    const int*   __restrict__ topo,
    float*       __restrict__ out) {

    extern __shared__ float sm[];
    float* table = sm;                          // N*12 floats

    int tid  = threadIdx.x;
    int warp = tid >> 5;
    int lane = tid & 31;
    int g    = lane >> 3;                       // bn tile within warp (0..3)
    int s    = lane & 7;                        // sub-lane within tile (0..7)

    int b = blockIdx.x >> 3;                    // 8 blocks per batch

    // --- build batch frame table in smem (coalesced float4 loads) ---
    {
        const float4* fr4 = (const float4*)(frames_rot + (size_t)b * N * 9);
        for (int i = tid; i < N * 9 / 4; i += THREADS) {
            float4 v = fr4[i];
            int e = 4 * i;
#pragma unroll
            for (int u = 0; u < 4; u++) {
                int el = e + u;
                int fi = el / 9, c = el - fi * 9;
                table[fi * 12 + c] = (&v.x)[u];
            }
        }
        const float4* ft4 = (const float4*)(frames_trans + (size_t)b * N * 3);
        for (int i = tid; i < N * 3 / 4; i += THREADS) {
            float4 v = ft4[i];
            int e = 4 * i;
#pragma unroll
            for (int u = 0; u < 4; u++) {
                int el = e + u;
                int fi = el / 3, c = el - fi * 3;
                table[fi * 12 + 9 + c] = (&v.x)[u];
            }
        }
    }
    __syncthreads();

    float* buf  = sm + TABLE_FLOATS + warp * STAGE_FLOATS;  // rot quarter: 288 floats
    float* tbuf = buf + 288;                                // trans quarter: 96 floats
    float4* b4 = (float4*)buf;                              // 72 float4
    float4* t4 = (float4*)tbuf;                             // 24 float4

    int chunk = blockIdx.x * WARPS + warp;      // 0..2047 (exactly 2048 chunks)
    size_t chunkbn = (size_t)chunk * 32;

    const float4* pr4 = (const float4*)pair_rot;
    const float4* pt4 = (const float4*)pair_trans;

    float stash[13];

    // precompute lane mapping for staging loads
    int xa = lane;            int ta_t = xa / 18, ta_w = xa - ta_t * 18;
    int xb = lane + 32;       int tb_t = xb / 18, tb_w = xb - tb_t * 18;
    int xc = lane + 64;       int tc_t = xc / 18, tc_w = xc - tc_t * 18;   // lanes < 8
    int tt_t = lane / 6,      tt_w = lane - tt_t * 6;                      // lanes < 24

    for (int it = 0; it < 8; it++) {
        size_t bn0 = chunkbn + it * 4;
        size_t bng = bn0 + g;

        // --- conf & topo for this lane's 4 neighbors (one per quarter) ---
        const float* cfb = conf + bng * K;
        const int*   tpb = topo + bng * K;
        float wgt[4];
        int   jj[4];
#pragma unroll
        for (int q = 0; q < 4; q++) {
            wgt[q] = cfb[8 * q + s];
            jj[q]  = tpb[8 * q + s];
        }

        float acc[13];
#pragma unroll
        for (int v = 0; v < 13; v++) acc[v] = 0.0f;

#pragma unroll
        for (int q = 0; q < 4; q++) {
            // --- issue streaming loads for this quarter (coalesced) ---
            size_t rbase = bn0 * 72 + 18 * q;
            float4 ra = pr4[rbase + (size_t)ta_t * 72 + ta_w];
            float4 rb = pr4[rbase + (size_t)tb_t * 72 + tb_w];
            float4 rc;
            if (lane < 8) rc = pr4[rbase + (size_t)tc_t * 72 + tc_w];
            float4 tv;
            if (lane < 24) tv = pt4[bn0 * 24 + 6 * q + (size_t)tt_t * 24 + tt_w];

            // --- gather this lane's frame from the smem table (LDS.128) ---
            const float4* F = (const float4*)(table + (size_t)jj[q] * 12);
            float4 f0 = F[0], f1 = F[1], f2 = F[2];

            __syncwarp();                 // previous quarter fully consumed
            b4[lane]      = ra;
            b4[lane + 32] = rb;
            if (lane < 8)  b4[lane + 64] = rc;
            if (lane < 24) t4[lane] = tv;
            __syncwarp();                 // quarter staged

            // --- consume: neighbor k = 8q + s of tile g ---
            const float* P = buf  + g * 72 + s * 9;   // all-distinct banks
            const float* Q = tbuf + g * 24 + s * 3;   // all-distinct banks

            float w = wgt[q];
            float R0x = f0.x, R0y = f0.y, R0z = f0.z;
            float R1x = f0.w, R1y = f1.x, R1z = f1.y;
            float R2x = f1.z, R2y = f1.w, R2z = f2.x;
            float tx  = f2.y, ty  = f2.z, tz  = f2.w;

#pragma unroll
            for (int c = 0; c < 3; c++) {
                float p0 = P[c], p1 = P[3 + c], p2 = P[6 + c];
                acc[0 + c] += w * (R0x * p0 + R0y * p1 + R0z * p2);
                acc[3 + c] += w * (R1x * p0 + R1y * p1 + R1z * p2);
                acc[6 + c] += w * (R2x * p0 + R2y * p1 + R2z * p2);
            }
            float q0 = Q[0], q1 = Q[1], q2 = Q[2];
            acc[9]  += w * (R0x * q0 + R0y * q1 + R0z * q2 + tx);
            acc[10] += w * (R1x * q0 + R1y * q1 + R1z * q2 + ty);
            acc[11] += w * (R2x * q0 + R2y * q1 + R2z * q2 + tz);
            acc[12] += w;
        }
        __syncwarp();

        // --- butterfly reduce within 8-lane groups (result in all lanes) ---
#pragma unroll
        for (int v = 0; v < 13; v++) {
            acc[v] += __shfl_xor_sync(0xffffffffu, acc[v], 4);
            acc[v] += __shfl_xor_sync(0xffffffffu, acc[v], 2);
            acc[v] += __shfl_xor_sync(0xffffffffu, acc[v], 1);
        }

        // --- stash: lane L = it*4 + g' collects group g' of iteration it ---
        int src = (lane & 3) * 8;
#pragma unroll
        for (int v = 0; v < 13; v++) {
            float tmp = __shfl_sync(0xffffffffu, acc[v], src);
            if ((lane >> 2) == it) stash[v] = tmp;
        }
    }

    // --- epilogue: 32 fully-parallel SVDs, one bn per lane ---
    float4* o = (float4*)out + (chunkbn + lane) * 3;
    svd_project_write(stash, o);
}

// ---------------------------------------------------------------------------
extern "C" void kernel_launch(void* const* d_in, const int* in_sizes, int n_in,
                              void* d_out, int out_size) {
    const float* frames_rot   = (const float*)d_in[0];
    const float* frames_trans = (const float*)d_in[1];
    const float* pair_rot     = (const float*)d_in[2];
    const float* pair_trans   = (const float*)d_in[3];
    const float* confidences  = (const float*)d_in[4];
    const int*   topology     = (const int*)d_in[5];
    float*       out          = (float*)d_out;

    cudaFuncSetAttribute(fused_backbone_kernel,
                         cudaFuncAttributeMaxDynamicSharedMemorySize, SMEM_BYTES);

    fused_backbone_kernel<<<BN / (WARPS * 32), THREADS, SMEM_BYTES>>>(
        frames_rot, frames_trans, pair_rot, pair_trans,
        confidences, topology, out);
}